// round 12
// baseline (speedup 1.0000x reference)
#include <cuda_runtime.h>
#include <cstdint>

// LengthRegulator via TMA bulk copies, single fused kernel.
// ys[b, f, :] = xs[b, i, :] where cum[b,i-1] <= f < cum[b,i], else 0.
//
// Per block (16 frames): shuffle-scan ds[b,:] -> scatter frame->row map.
// Warp 0 lanes 0-15: run-length dedup (ballot), head lanes TMA-load their
// distinct source row into a shared slot (mbarrier tx-counted), then every
// lane TMA-stores its frame's slot (or a zero slot) to the output. No
// per-lane LDG/STG of payload data at all.

#define BATCH    8
#define TIN      512
#define TOUT     4096
#define DIM4     96
#define ROWBYTES (DIM4 * 16)        // 1536 B per row/frame
#define FPB      16                 // frames per block
#define THREADS  512
#define ZSLOT    FPB                // zero-fill slot index

static __device__ __forceinline__ uint32_t smem_u32(const void* p) {
    uint32_t a;
    asm("{ .reg .u64 t; cvta.to.shared.u64 t, %1; cvt.u32.u64 %0, t; }"
        : "=r"(a) : "l"(p));
    return a;
}

__global__ __launch_bounds__(THREADS, 4)
void lr_tma(const float4* __restrict__ xs,
            const int* __restrict__ ds,
            float4* __restrict__ out)
{
    __shared__ __align__(128) float4 s_buf[FPB + 1][DIM4];   // 17*1536 B
    __shared__ int s_wsum[16];
    __shared__ int s_map[FPB];
    __shared__ __align__(8) unsigned long long s_mbar;

    const int b      = blockIdx.x;
    const int frame0 = blockIdx.y * FPB;
    const int tid    = threadIdx.x;
    const int lane   = tid & 31;
    const int wid    = tid >> 5;

    // ---- scan prologue (validated R4-R11) ----
    const int d = ds[b * TIN + tid];
    int v = d;
#pragma unroll
    for (int off = 1; off < 32; off <<= 1) {
        int n = __shfl_up_sync(0xffffffffu, v, off);
        if (lane >= off) v += n;
    }
    if (lane == 31) s_wsum[wid] = v;
    if (tid < FPB)  s_map[tid] = -1;
    if (tid == 0) {
        uint32_t mb = smem_u32(&s_mbar);
        asm volatile("mbarrier.init.shared.b64 [%0], 1;" :: "r"(mb) : "memory");
    }
    if (tid < DIM4) {
        s_buf[ZSLOT][tid] = make_float4(0.f, 0.f, 0.f, 0.f);
        asm volatile("fence.proxy.async.shared::cta;" ::: "memory");
    }
    __syncthreads();

    if (wid == 0 && lane < 16) {
        int w = s_wsum[lane];
#pragma unroll
        for (int off = 1; off < 16; off <<= 1) {
            int n = __shfl_up_sync(0x0000ffffu, w, off);
            if (lane >= off) w += n;
        }
        s_wsum[lane] = w;
    }
    __syncthreads();

    const int cum  = v + (wid > 0 ? s_wsum[wid - 1] : 0);
    const int left = cum - d;
    int lo = left < frame0 ? frame0 : left;
    int hi = cum  > frame0 + FPB ? frame0 + FPB : cum;
    for (int f = lo; f < hi; f++)
        s_map[f - frame0] = tid;
    __syncthreads();

    // ---- TMA copy: warp 0, lanes 0..15 (lane == frame-in-block) ----
    if (wid == 0 && lane < FPB) {
        const uint32_t mb = smem_u32(&s_mbar);

        const int  m    = s_map[lane];
        const int  prev = __shfl_up_sync(0x0000ffffu, m, 1);
        const bool head = (lane == 0) || (m != prev);
        const uint32_t hm       = __ballot_sync(0x0000ffffu, head);
        const uint32_t loadmask = __ballot_sync(0x0000ffffu, head && m >= 0);
        const int  slot = __popc(hm & ((2u << lane) - 1u)) - 1;

        if (lane == 0) {
            const uint32_t tx = __popc(loadmask) * ROWBYTES;
            asm volatile("mbarrier.arrive.expect_tx.shared.b64 _, [%0], %1;"
                         :: "r"(mb), "r"(tx) : "memory");
        }
        __syncwarp(0x0000ffffu);

        // distinct source rows -> shared slots (run-length dedup)
        if (head && m >= 0) {
            const char* src = (const char*)(xs + (size_t)(b * TIN + m) * DIM4);
            uint32_t dst = smem_u32(&s_buf[slot][0]);
            uint32_t sz  = ROWBYTES;
            asm volatile(
                "cp.async.bulk.shared::cta.global.mbarrier::complete_tx::bytes"
                " [%0], [%1], %2, [%3];"
                :: "r"(dst), "l"(src), "r"(sz), "r"(mb) : "memory");
        }

        // wait for all loads (parity 0, single-phase use)
        asm volatile(
            "{\n\t"
            ".reg .pred P;\n\t"
            "LR_WAIT_%=:\n\t"
            "mbarrier.try_wait.parity.acquire.cta.shared::cta.b64 P, [%0], 0, 0x989680;\n\t"
            "@P bra.uni LR_DONE_%=;\n\t"
            "bra.uni LR_WAIT_%=;\n\t"
            "LR_DONE_%=:\n\t"
            "}"
            :: "r"(mb) : "memory");

        // every lane stores its frame from its run's slot (or zero slot)
        const int myslot = (m >= 0) ? slot : ZSLOT;
        uint32_t src = smem_u32(&s_buf[myslot][0]);
        char* dstg = (char*)(out + (size_t)(b * TOUT + frame0 + lane) * DIM4);
        uint32_t sz = ROWBYTES;
        asm volatile("cp.async.bulk.global.shared::cta.bulk_group [%0], [%1], %2;"
                     :: "l"(dstg), "r"(src), "r"(sz) : "memory");
        asm volatile("cp.async.bulk.commit_group;" ::: "memory");
        asm volatile("cp.async.bulk.wait_group 0;" ::: "memory");
    }
}

extern "C" void kernel_launch(void* const* d_in, const int* in_sizes, int n_in,
                              void* d_out, int out_size)
{
    const float* xs = (const float*)d_in[0];
    const int*   ds = (const int*)d_in[1];
    float*       out = (float*)d_out;

    dim3 grid(BATCH, TOUT / FPB);   // 8 x 256 = 2048 blocks
    lr_tma<<<grid, THREADS>>>((const float4*)xs, ds, (float4*)out);
}

// round 13
// speedup vs baseline: 1.2882x; 1.2882x over previous
#include <cuda_runtime.h>

// LengthRegulator, fused single kernel:
// ys[b, f, :] = xs[b, i, :] where cum[b,i-1] <= f < cum[b,i], else 0.
//
// 256-thread blocks, 32 frames each (R11's best-measured copy geometry,
// now single-launch). Inline pair-sum shuffle scan (2 ds elems/thread),
// scatter frame->row map to shared, then warp-per-4-frames copy with
// run-length source-load elimination and streaming (__stcs) stores.

#define BATCH   8
#define TIN     512
#define TOUT    4096
#define DIM4    96                  // 384/4 float4 per row
#define FPB     32                  // frames per block
#define THREADS 256                 // 8 warps
#define FPW     4                   // frames per warp

__device__ float4 g_zero[DIM4];     // stays zero (never written)

__global__ __launch_bounds__(THREADS, 8)
void lr_fused(const float4* __restrict__ xs,
              const int* __restrict__ ds,
              float4* __restrict__ out)
{
    __shared__ int s_wsum[8];
    __shared__ int s_map[FPB];

    const int b      = blockIdx.x;
    const int frame0 = blockIdx.y * FPB;
    const int tid    = threadIdx.x;
    const int lane   = tid & 31;
    const int wid    = tid >> 5;

    // ---- inline scan: thread t owns ds rows 2t, 2t+1 ----
    const int2 dd = ((const int2*)(ds + b * TIN))[tid];
    const int  pair = dd.x + dd.y;

    int v = pair;                   // inclusive scan of pair-sums
#pragma unroll
    for (int off = 1; off < 32; off <<= 1) {
        int n = __shfl_up_sync(0xffffffffu, v, off);
        if (lane >= off) v += n;
    }
    if (lane == 31) s_wsum[wid] = v;
    if (tid < FPB)  s_map[tid] = -1;
    __syncthreads();

    if (wid == 0 && lane < 8) {
        int w = s_wsum[lane];
#pragma unroll
        for (int off = 1; off < 8; off <<= 1) {
            int n = __shfl_up_sync(0x000000ffu, w, off);
            if (lane >= off) w += n;
        }
        s_wsum[lane] = w;           // inclusive warp-prefix of pair-sums
    }
    __syncthreads();

    const int cum1  = v + (wid > 0 ? s_wsum[wid - 1] : 0); // incl cum of row 2t+1
    const int cum0  = cum1 - dd.y;                         // incl cum of row 2t
    const int left0 = cum0 - dd.x;

    // scatter rows 2t and 2t+1 into this block's 32-frame window
    const int fend = frame0 + FPB;
    {
        int lo = left0 < frame0 ? frame0 : left0;
        int hi = cum0  > fend   ? fend   : cum0;
        for (int f = lo; f < hi; f++) s_map[f - frame0] = 2 * tid;
        lo = cum0 < frame0 ? frame0 : cum0;
        hi = cum1 > fend   ? fend   : cum1;
        for (int f = lo; f < hi; f++) s_map[f - frame0] = 2 * tid + 1;
    }
    __syncthreads();

    // ---- copy: warp w owns frames [frame0 + w*FPW, +FPW) ----
    const float4* __restrict__ xsb = xs + (size_t)b * TIN * DIM4;
    const int fbase = wid * FPW;
    float4* __restrict__ o =
        out + (size_t)(b * TOUT + frame0 + fbase) * DIM4 + lane;

    int prev_row = -2;
    float4 a0, a1, a2;
#pragma unroll
    for (int k = 0; k < FPW; k++) {
        const int row = s_map[fbase + k];          // warp-uniform
        if (row != prev_row) {                     // uniform branch
            const float4* p = (row >= 0) ? (xsb + row * DIM4) : g_zero;
            a0 = p[lane];
            a1 = p[lane + 32];
            a2 = p[lane + 64];
            prev_row = row;
        }
        __stcs(o + k * DIM4,      a0);             // streaming: write-once data
        __stcs(o + k * DIM4 + 32, a1);
        __stcs(o + k * DIM4 + 64, a2);
    }
}

extern "C" void kernel_launch(void* const* d_in, const int* in_sizes, int n_in,
                              void* d_out, int out_size)
{
    const float* xs = (const float*)d_in[0];
    const int*   ds = (const int*)d_in[1];
    float*       out = (float*)d_out;

    dim3 grid(BATCH, TOUT / FPB);   // 8 x 128 = 1024 blocks
    lr_fused<<<grid, THREADS>>>((const float4*)xs, ds, (float4*)out);
}